// round 2
// baseline (speedup 1.0000x reference)
#include <cuda_runtime.h>

#define LDD 192
#define M_TOTAL 64000
typedef unsigned long long u64;

// ---------------- scratch (static device globals; no allocation) ----------------
static __device__ float g_A[(size_t)M_TOTAL * LDD];   // 49 MB
static __device__ float g_B[(size_t)M_TOTAL * LDD];   // 49 MB
static __device__ float g_G[LDD * LDD];
static __device__ float g_T[LDD * LDD];
static __device__ float g_Pt[LDD * LDD];
static __device__ float g_Wp[LDD * LDD];

__device__ __forceinline__ void ffma2(u64 &d, u64 a, u64 b) {
  asm volatile("fma.rn.f32x2 %0, %1, %2, %0;" : "+l"(d) : "l"(a), "l"(b));
}

// ---------------- per-branch compile-time traits ----------------
template<int BR> struct Tr;
template<> struct Tr<0> { // axi: s=(48,66,38) w=(5,7,4) d=140 pb=(1,2,1)
  static constexpr int w0=5,w1=7,w2=4,d=140;
  static constexpr int s0=48,s1=66,s2=38;
  static constexpr int pb0=1,pb1=2,pb2=1;
  static constexpr long OFF=0;
};
template<> struct Tr<1> { // cor (internal transpose 0,1,2,4,3): s=(38,38,66) w=(4,4,7) d=112 pb=(1,1,2)
  static constexpr int w0=4,w1=4,w2=7,d=112;
  static constexpr int s0=38,s1=38,s2=66;
  static constexpr int pb0=1,pb1=1,pb2=2;
  static constexpr long OFF=7704576;
};
template<> struct Tr<2> { // sag (internal transpose 0,1,4,3,2): s=(38,78,48) w=(4,8,5) d=160 pb=(1,1,1)
  static constexpr int w0=4,w1=8,w2=5,d=160;
  static constexpr int s0=38,s1=78,s2=48;
  static constexpr int pb0=1,pb1=1,pb2=1;
  static constexpr long OFF=13804032;
};

template<int BR>
__device__ __forceinline__ void amap(int x, int y, int z, int& xb, int& yb, int& zb) {
  if (BR == 0) {
    xb = x; yb = (y * 6) / 7; zb = z;
  } else if (BR == 1) {
    int x2 = (x * 5) / 4, y2 = (y * 7) / 4, z2 = (z * 4) / 7;
    xb = x2; yb = (y2 * 6) / 7; zb = z2;
  } else {
    int y3 = y / 2, z3 = (z * 7) / 5;
    int x2 = (x * 5) / 4, y2 = (y3 * 7) / 4, z2 = (z3 * 4) / 7;
    xb = x2; yb = (y2 * 6) / 7; zb = z2;
  }
}

// ---------------- pack: gather A-hat and B-hat ----------------
template<int BR>
__global__ void pack_kernel(const float* __restrict__ feat, const float* __restrict__ atlas) {
  constexpr int w1=Tr<BR>::w1, w2=Tr<BR>::w2, d=Tr<BR>::d;
  constexpr int s0=Tr<BR>::s0, s1=Tr<BR>::s1, s2=Tr<BR>::s2;
  constexpr int pb0=Tr<BR>::pb0, pb1=Tr<BR>::pb1, pb2=Tr<BR>::pb2;
  constexpr int w0=Tr<BR>::w0;
  int blk = blockIdx.x;
  int c = blk / 100;
  int a = (blk / 10) % 10;
  int b = blk % 10;
  for (int t = threadIdx.x; t < 10 * LDD; t += blockDim.x) {
    int cc = t / LDD;
    int j  = t - cc * LDD;
    int row = blk * 10 + cc;
    float vB, vA;
    if (j < d) {
      int x = j / (w1 * w2);
      int y = (j / w2) % w1;
      int z = j % w2;
      int i0 = a * w0 + x - pb0;
      int i1 = b * w1 + y - pb1;
      int i2 = cc * w2 + z - pb2;
      vB = 0.f;
      if ((unsigned)i0 < (unsigned)s0 && (unsigned)i1 < (unsigned)s1 && (unsigned)i2 < (unsigned)s2) {
        int src;
        if (BR == 0)      src = ((c * 48 + i0) * 66 + i1) * 38 + i2;
        else if (BR == 1) src = ((c * 38 + i0) * 66 + i2) * 38 + i1;
        else              src = ((c * 48 + i2) * 78 + i1) * 38 + i0;
        vB = feat[src];
      }
      int xb, yb, zb;
      amap<BR>(x, y, z, xb, yb, zb);
      int j0 = a * 5 + xb - 2;
      int j1 = b * 6 + yb - 2;
      int j2 = cc * 4 + zb - 1;
      vA = 0.f;
      if ((unsigned)j0 < 46u && (unsigned)j1 < 56u && (unsigned)j2 < 38u)
        vA = atlas[((c * 46 + j0) * 56 + j1) * 38 + j2];
    } else {
      vB = (j == d) ? 1.f : 0.f;
      vA = vB;
    }
    g_B[row * LDD + j] = vB;
    g_A[row * LDD + j] = vA;
  }
}

__global__ void zero_kernel() {
  int i = blockIdx.x * blockDim.x + threadIdx.x;
  if (i < LDD * LDD) { g_G[i] = 0.f; g_Wp[i] = 0.f; }
}

// ---------------- GEMM1: G = A-hat^T * B-hat, split-K, f32x2 ----------------
__global__ void gemm1_kernel(int mChunk) {
  int p0 = blockIdx.x * 64;
  int q0 = blockIdx.y * 64;
  int m0 = blockIdx.z * mChunk;
  int mHi = min(m0 + mChunk, M_TOTAL);
  __shared__ alignas(16) float As2[16][128];   // p-side, duplicated pairs
  __shared__ alignas(16) float Bs[16][64];     // q-side
  u64 acc[4][2] = {};
  int t = threadIdx.x;
  int tx = t & 15, ty = t >> 4;
  int lk = ty, lc = tx * 4;
  float4 a4 = make_float4(0.f,0.f,0.f,0.f);
  float4 b4 = a4;
  if (m0 + lk < mHi) {
    a4 = *(const float4*)(g_A + (size_t)(m0 + lk) * LDD + p0 + lc);
    b4 = *(const float4*)(g_B + (size_t)(m0 + lk) * LDD + q0 + lc);
  }
  for (int mb = m0; mb < mHi; mb += 16) {
    __syncthreads();
    *(float4*)&As2[lk][lc * 2]     = make_float4(a4.x, a4.x, a4.y, a4.y);
    *(float4*)&As2[lk][lc * 2 + 4] = make_float4(a4.z, a4.z, a4.w, a4.w);
    *(float4*)&Bs[lk][lc] = b4;
    __syncthreads();
    int mn = mb + 16;
    a4 = make_float4(0.f,0.f,0.f,0.f); b4 = a4;
    if (mn + lk < mHi) {
      a4 = *(const float4*)(g_A + (size_t)(mn + lk) * LDD + p0 + lc);
      b4 = *(const float4*)(g_B + (size_t)(mn + lk) * LDD + q0 + lc);
    }
#pragma unroll
    for (int k = 0; k < 16; k++) {
      ulonglong2 a01 = *(ulonglong2*)&As2[k][ty * 8];
      ulonglong2 a23 = *(ulonglong2*)&As2[k][ty * 8 + 4];
      ulonglong2 bp  = *(ulonglong2*)&Bs[k][tx * 4];
      ffma2(acc[0][0], a01.x, bp.x); ffma2(acc[0][1], a01.x, bp.y);
      ffma2(acc[1][0], a01.y, bp.x); ffma2(acc[1][1], a01.y, bp.y);
      ffma2(acc[2][0], a23.x, bp.x); ffma2(acc[2][1], a23.x, bp.y);
      ffma2(acc[3][0], a23.y, bp.x); ffma2(acc[3][1], a23.y, bp.y);
    }
  }
#pragma unroll
  for (int i = 0; i < 4; i++)
#pragma unroll
    for (int jp = 0; jp < 2; jp++) {
      float2 v = *(float2*)&acc[i][jp];
      int rr = (p0 + ty * 4 + i) * LDD + q0 + tx * 4 + jp * 2;
      atomicAdd(&g_G[rr],     v.x);
      atomicAdd(&g_G[rr + 1], v.y);
    }
}

// ---------------- small chain: T = G-hat @ Wk-hat ----------------
__global__ void k3a_kernel(const float* __restrict__ Wk, const float* __restrict__ bk, int d) {
  int r = blockIdx.x;                  // [0, D)
  __shared__ float gsh[192];
  int t = threadIdx.x;                 // 192
  int D = d + 1;
  gsh[t] = (t < D) ? g_G[r * LDD + t] : 0.f;
  __syncthreads();
  if (t < d) {
    float s = gsh[d] * bk[t];
#pragma unroll 4
    for (int ss = 0; ss < d; ss++) s += gsh[ss] * Wk[ss * d + t];
    g_T[r * LDD + t] = s;
  }
}

// S row p = Wq-hat[:,p]^T @ T, fused softmax, write P transposed
__global__ void k3b_kernel(const float* __restrict__ Wq, const float* __restrict__ bq, int d) {
  int p = blockIdx.x;                  // [0, d)
  __shared__ float wq[192];
  __shared__ float red[256];
  int t = threadIdx.x;                 // 256
  int D = d + 1;
  if (t < 192) wq[t] = (t < d) ? Wq[t * d + p] : ((t == d) ? bq[p] : 0.f);
  __syncthreads();
  float s = -3.0e38f;
  if (t < d) {
    s = 0.f;
#pragma unroll 4
    for (int r = 0; r < D; r++) s += wq[r] * g_T[r * LDD + t];
  }
  red[t] = s; __syncthreads();
  for (int o = 128; o > 0; o >>= 1) { if (t < o) red[t] = fmaxf(red[t], red[t + o]); __syncthreads(); }
  float mx = red[0]; __syncthreads();
  float e = (t < d) ? expf(s - mx) : 0.f;
  red[t] = e; __syncthreads();
  for (int o = 128; o > 0; o >>= 1) { if (t < o) red[t] += red[t + o]; __syncthreads(); }
  float inv = 1.f / red[0];
  if (t < d) g_Pt[t * LDD + p] = e * inv;
}

// W' row j = Wv-hat[j,:] @ P^T  (uses Pt for coalesced reads)
__global__ void k3d_kernel(const float* __restrict__ Wv, const float* __restrict__ bv, int d) {
  int j = blockIdx.x;                  // [0, D)
  __shared__ float wv[192];
  int t = threadIdx.x;                 // 192
  if (t < d) wv[t] = (j < d) ? Wv[j * d + t] : bv[t];
  __syncthreads();
  if (t < d) {
    float s = 0.f;
#pragma unroll 4
    for (int l = 0; l < d; l++) s += wv[l] * g_Pt[l * LDD + t];
    g_Wp[j * LDD + t] = s;
  }
}

// ---------------- GEMM2: cross = B-hat @ W', f32x2, fused scatter epilogue ----------------
template<int BR>
__global__ void gemm2_kernel(float* __restrict__ out) {
  constexpr int d  = Tr<BR>::d;
  constexpr int w0 = Tr<BR>::w0, w1 = Tr<BR>::w1, w2 = Tr<BR>::w2;
  constexpr int s0 = Tr<BR>::s0, s1 = Tr<BR>::s1, s2 = Tr<BR>::s2;
  constexpr int pb0 = Tr<BR>::pb0, pb1 = Tr<BR>::pb1, pb2 = Tr<BR>::pb2;
  constexpr int KK = ((d + 1 + 15) / 16) * 16;
  int m0 = blockIdx.x * 64;
  int n0 = blockIdx.y * 64;
  __shared__ alignas(16) float Bs2[16][128];   // row-side (m), duplicated pairs, transposed
  __shared__ alignas(16) float Ws[16][64];
  u64 acc[4][2] = {};
  int t = threadIdx.x;
  int tx = t & 15, ty = t >> 4;
  int brow = t >> 2, bkg = (t & 3) * 4;
  int lk = ty, lc = tx * 4;
  float4 b4 = *(const float4*)(g_B + (size_t)(m0 + brow) * LDD + bkg);
  float4 w4 = *(const float4*)(g_Wp + (size_t)lk * LDD + n0 + lc);
  for (int k0 = 0; k0 < KK; k0 += 16) {
    __syncthreads();
    *(float2*)&Bs2[bkg + 0][2 * brow] = make_float2(b4.x, b4.x);
    *(float2*)&Bs2[bkg + 1][2 * brow] = make_float2(b4.y, b4.y);
    *(float2*)&Bs2[bkg + 2][2 * brow] = make_float2(b4.z, b4.z);
    *(float2*)&Bs2[bkg + 3][2 * brow] = make_float2(b4.w, b4.w);
    *(float4*)&Ws[lk][lc] = w4;
    __syncthreads();
    int kn = k0 + 16;
    if (kn < KK) {
      b4 = *(const float4*)(g_B + (size_t)(m0 + brow) * LDD + kn + bkg);
      w4 = *(const float4*)(g_Wp + (size_t)(kn + lk) * LDD + n0 + lc);
    }
#pragma unroll
    for (int k = 0; k < 16; k++) {
      ulonglong2 a01 = *(ulonglong2*)&Bs2[k][ty * 8];
      ulonglong2 a23 = *(ulonglong2*)&Bs2[k][ty * 8 + 4];
      ulonglong2 wp  = *(ulonglong2*)&Ws[k][tx * 4];
      ffma2(acc[0][0], a01.x, wp.x); ffma2(acc[0][1], a01.x, wp.y);
      ffma2(acc[1][0], a01.y, wp.x); ffma2(acc[1][1], a01.y, wp.y);
      ffma2(acc[2][0], a23.x, wp.x); ffma2(acc[2][1], a23.x, wp.y);
      ffma2(acc[3][0], a23.y, wp.x); ffma2(acc[3][1], a23.y, wp.y);
    }
  }
  // epilogue: fold + crop + branch transpose, direct to output
#pragma unroll
  for (int i = 0; i < 4; i++) {
    int m = m0 + ty * 4 + i;
    int c  = m / 1000;
    int rem = m - c * 1000;
    int a  = rem / 100;
    int b  = (rem / 10) % 10;
    int cc = rem % 10;
#pragma unroll
    for (int jp = 0; jp < 2; jp++) {
      float2 v = *(float2*)&acc[i][jp];
#pragma unroll
      for (int h = 0; h < 2; h++) {
        int col = n0 + tx * 4 + jp * 2 + h;
        float val = h ? v.y : v.x;
        if (col < d) {
          int x = col / (w1 * w2);
          int y = (col / w2) % w1;
          int z = col % w2;
          int u0 = a * w0 + x - pb0;
          int u1 = b * w1 + y - pb1;
          int u2 = cc * w2 + z - pb2;
          if ((unsigned)u0 < (unsigned)s0 && (unsigned)u1 < (unsigned)s1 && (unsigned)u2 < (unsigned)s2) {
            long dst;
            if (BR == 0)      dst = ((long)(c * 48 + u0) * 66 + u1) * 38 + u2;
            else if (BR == 1) dst = ((long)(c * 38 + u0) * 66 + u2) * 38 + u1;
            else              dst = ((long)(c * 48 + u2) * 78 + u1) * 38 + u0;
            out[Tr<BR>::OFF + dst] = val;
          }
        }
      }
    }
  }
}

// ---------------- host-side branch driver ----------------
template<int BR>
static void run_branch(const float* feat, const float* atlas,
                       const float* Wq, const float* bq,
                       const float* Wk, const float* bk,
                       const float* Wv, const float* bv,
                       float* out) {
  constexpr int d  = Tr<BR>::d;
  constexpr int D  = d + 1;
  constexpr int NT = (D + 63) / 64;
  constexpr int NS = (296 + NT * NT - 1) / (NT * NT);
  constexpr int CHUNK = (M_TOTAL + NS - 1) / NS;
  constexpr int NTn = (d + 63) / 64;
  pack_kernel<BR><<<6400, 256>>>(feat, atlas);
  zero_kernel<<<(LDD * LDD + 255) / 256, 256>>>();
  gemm1_kernel<<<dim3(NT, NT, NS), 256>>>(CHUNK);
  k3a_kernel<<<D, 192>>>(Wk, bk, d);
  k3b_kernel<<<d, 256>>>(Wq, bq, d);
  k3d_kernel<<<D, 192>>>(Wv, bv, d);
  gemm2_kernel<BR><<<dim3(1000, NTn), 256>>>(out);
}

extern "C" void kernel_launch(void* const* d_in, const int* in_sizes, int n_in,
                              void* d_out, int out_size) {
  const float* axi   = (const float*)d_in[0];
  const float* cor   = (const float*)d_in[1];
  const float* sag   = (const float*)d_in[2];
  const float* atlas = (const float*)d_in[3];
  float* out = (float*)d_out;
  run_branch<0>(axi, atlas,
                (const float*)d_in[4],  (const float*)d_in[5],
                (const float*)d_in[6],  (const float*)d_in[7],
                (const float*)d_in[8],  (const float*)d_in[9], out);
  run_branch<1>(cor, atlas,
                (const float*)d_in[10], (const float*)d_in[11],
                (const float*)d_in[12], (const float*)d_in[13],
                (const float*)d_in[14], (const float*)d_in[15], out);
  run_branch<2>(sag, atlas,
                (const float*)d_in[16], (const float*)d_in[17],
                (const float*)d_in[18], (const float*)d_in[19],
                (const float*)d_in[20], (const float*)d_in[21], out);
}

// round 5
// speedup vs baseline: 1.1796x; 1.1796x over previous
#include <cuda_runtime.h>

#define LDD 192
#define M_TOTAL 64000
#define AB_STRIDE ((size_t)M_TOTAL * LDD)
#define GSTRIDE (LDD * LDD)

// ---------------- scratch (static device globals; no allocation) ----------------
static __device__ float g_B[3 * AB_STRIDE];   // ~147 MB (branch-batched)
static __device__ float g_A[AB_STRIDE];       // ~49 MB (shared, per-branch reuse)
static __device__ float g_G[3 * GSTRIDE];
static __device__ float g_T[3 * GSTRIDE];
static __device__ float g_Pt[3 * GSTRIDE];
static __device__ float g_Wp[3 * GSTRIDE];

// ---------------- per-branch compile-time traits ----------------
template<int BR> struct Tr;
template<> struct Tr<0> { // axi: s=(48,66,38) w=(5,7,4) d=140 pb=(1,2,1)
  static constexpr int w0=5,w1=7,w2=4,d=140,nt=3;
  static constexpr int s0=48,s1=66,s2=38;
  static constexpr int pb0=1,pb1=2,pb2=1;
  static constexpr long OFF=0;
};
template<> struct Tr<1> { // cor (internal transpose 0,1,2,4,3): s=(38,38,66) w=(4,4,7) d=112 pb=(1,1,2)
  static constexpr int w0=4,w1=4,w2=7,d=112,nt=2;
  static constexpr int s0=38,s1=38,s2=66;
  static constexpr int pb0=1,pb1=1,pb2=2;
  static constexpr long OFF=7704576;
};
template<> struct Tr<2> { // sag (internal transpose 0,1,4,3,2): s=(38,78,48) w=(4,8,5) d=160 pb=(1,1,1)
  static constexpr int w0=4,w1=8,w2=5,d=160,nt=3;
  static constexpr int s0=38,s1=78,s2=48;
  static constexpr int pb0=1,pb1=1,pb2=1;
  static constexpr long OFF=13804032;
};

template<int BR>
__device__ __forceinline__ void amap(int x, int y, int z, int& xb, int& yb, int& zb) {
  if (BR == 0) {
    xb = x; yb = (y * 6) / 7; zb = z;
  } else if (BR == 1) {
    int x2 = (x * 5) / 4, y2 = (y * 7) / 4, z2 = (z * 4) / 7;
    xb = x2; yb = (y2 * 6) / 7; zb = z2;
  } else {
    int y3 = y / 2, z3 = (z * 7) / 5;
    int x2 = (x * 5) / 4, y2 = (y3 * 7) / 4, z2 = (z3 * 4) / 7;
    xb = x2; yb = (y2 * 6) / 7; zb = z2;
  }
}

// ---------------- packB: gather B-hat for all branches in one launch ----------------
template<int BR>
__device__ void packB_body(const float* __restrict__ feat) {
  constexpr int w0=Tr<BR>::w0, w1=Tr<BR>::w1, w2=Tr<BR>::w2, d=Tr<BR>::d;
  constexpr int s0=Tr<BR>::s0, s1=Tr<BR>::s1, s2=Tr<BR>::s2;
  constexpr int pb0=Tr<BR>::pb0, pb1=Tr<BR>::pb1, pb2=Tr<BR>::pb2;
  float* Bdst = g_B + (size_t)BR * AB_STRIDE;
  int blk = blockIdx.x;
  int c = blk / 100;
  int a = (blk / 10) % 10;
  int b = blk % 10;
  for (int t = threadIdx.x; t < 10 * LDD; t += blockDim.x) {
    int cc = t / LDD;
    int j  = t - cc * LDD;
    int row = blk * 10 + cc;
    float vB;
    if (j < d) {
      int x = j / (w1 * w2);
      int y = (j / w2) % w1;
      int z = j % w2;
      int i0 = a * w0 + x - pb0;
      int i1 = b * w1 + y - pb1;
      int i2 = cc * w2 + z - pb2;
      vB = 0.f;
      if ((unsigned)i0 < (unsigned)s0 && (unsigned)i1 < (unsigned)s1 && (unsigned)i2 < (unsigned)s2) {
        int src;
        if (BR == 0)      src = ((c * 48 + i0) * 66 + i1) * 38 + i2;
        else if (BR == 1) src = ((c * 38 + i0) * 66 + i2) * 38 + i1;
        else              src = ((c * 48 + i2) * 78 + i1) * 38 + i0;
        vB = feat[src];
      }
    } else {
      vB = (j == d) ? 1.f : 0.f;
    }
    Bdst[(size_t)row * LDD + j] = vB;
  }
}

__global__ void packB_all(const float* __restrict__ axi, const float* __restrict__ cor,
                          const float* __restrict__ sag) {
  if (blockIdx.y == 0)      packB_body<0>(axi);
  else if (blockIdx.y == 1) packB_body<1>(cor);
  else                      packB_body<2>(sag);
}

// ---------------- packA: gather A-hat for one branch into shared buffer ----------------
template<int BR>
__global__ void packA_kernel(const float* __restrict__ atlas) {
  constexpr int w1=Tr<BR>::w1, w2=Tr<BR>::w2, d=Tr<BR>::d;
  int blk = blockIdx.x;
  int a = (blk / 10) % 10;
  int b = blk % 10;
  int c = blk / 100;
  for (int t = threadIdx.x; t < 10 * LDD; t += blockDim.x) {
    int cc = t / LDD;
    int j  = t - cc * LDD;
    int row = blk * 10 + cc;
    float vA;
    if (j < d) {
      int x = j / (w1 * w2);
      int y = (j / w2) % w1;
      int z = j % w2;
      int xb, yb, zb;
      amap<BR>(x, y, z, xb, yb, zb);
      int j0 = a * 5 + xb - 2;   // atlas aw=(5,6,4), pb=(2,2,1)
      int j1 = b * 6 + yb - 2;
      int j2 = cc * 4 + zb - 1;
      vA = 0.f;
      if ((unsigned)j0 < 46u && (unsigned)j1 < 56u && (unsigned)j2 < 38u)
        vA = atlas[((c * 46 + j0) * 56 + j1) * 38 + j2];
    } else {
      vA = (j == d) ? 1.f : 0.f;
    }
    g_A[(size_t)row * LDD + j] = vA;
  }
}

__global__ void zero_all() {
  int i = blockIdx.x * blockDim.x + threadIdx.x;
  if (i < 3 * GSTRIDE) { g_G[i] = 0.f; g_Wp[i] = 0.f; }
}

// ---------------- GEMM1: G = A-hat^T * B-hat, one branch, split-M, 8x8 micro ----------------
template<int BR>
__global__ void __launch_bounds__(64, 8) gemm1_kernel(int mChunk) {
  int p0 = blockIdx.x * 64;
  int q0 = blockIdx.y * 64;
  int m0 = blockIdx.z * mChunk;
  int mHi = min(m0 + mChunk, M_TOTAL);
  if (m0 >= mHi) return;
  const float* A  = g_A;
  const float* Bp = g_B + (size_t)BR * AB_STRIDE;
  float* G = g_G + BR * GSTRIDE;
  __shared__ alignas(16) float As[16][64];
  __shared__ alignas(16) float Bs[16][64];
  float acc[8][8] = {};
  int t = threadIdx.x;               // 64 threads
  int tx = t & 7, ty = t >> 3;
  int lr = t >> 4, lc = (t & 15) * 4;
  float4 pa[4], pb[4];
#define G1_LD(MB)                                                        \
  {                                                                      \
    _Pragma("unroll")                                                    \
    for (int i = 0; i < 4; i++) {                                        \
      int row = (MB) + lr + i * 4;                                       \
      if (row < mHi) {                                                   \
        pa[i] = *(const float4*)(A  + (size_t)row * LDD + p0 + lc);      \
        pb[i] = *(const float4*)(Bp + (size_t)row * LDD + q0 + lc);      \
      } else { pa[i] = make_float4(0.f,0.f,0.f,0.f); pb[i] = pa[i]; }    \
    }                                                                    \
  }
  G1_LD(m0);
  for (int mb = m0; mb < mHi; mb += 16) {
    __syncthreads();
#pragma unroll
    for (int i = 0; i < 4; i++) {
      *(float4*)&As[lr + i * 4][lc] = pa[i];
      *(float4*)&Bs[lr + i * 4][lc] = pb[i];
    }
    __syncthreads();
    if (mb + 16 < mHi) G1_LD(mb + 16);
#pragma unroll
    for (int k = 0; k < 16; k++) {
      float a[8], b[8];
      *(float4*)&a[0] = *(float4*)&As[k][ty * 8];
      *(float4*)&a[4] = *(float4*)&As[k][ty * 8 + 4];
      *(float4*)&b[0] = *(float4*)&Bs[k][tx * 8];
      *(float4*)&b[4] = *(float4*)&Bs[k][tx * 8 + 4];
#pragma unroll
      for (int i = 0; i < 8; i++)
#pragma unroll
        for (int j = 0; j < 8; j++)
          acc[i][j] += a[i] * b[j];
    }
  }
#pragma unroll
  for (int i = 0; i < 8; i++)
#pragma unroll
    for (int j = 0; j < 8; j++)
      atomicAdd(&G[(p0 + ty * 8 + i) * LDD + q0 + tx * 8 + j], acc[i][j]);
#undef G1_LD
}

// ---------------- small chain (batched across branches) ----------------
struct P3 { const float* W0; const float* b0; const float* W1; const float* b1;
            const float* W2; const float* b2; };

__device__ __forceinline__ void sel(const P3& p, int br, const float*& W, const float*& b) {
  if (br == 0)      { W = p.W0; b = p.b0; }
  else if (br == 1) { W = p.W1; b = p.b1; }
  else              { W = p.W2; b = p.b2; }
}

// T = G-hat @ Wk-hat
__global__ void k3a_all(P3 pk) {
  const int dTab[3] = {140, 112, 160};
  int br = blockIdx.x / 161;
  int r  = blockIdx.x - br * 161;
  int d = dTab[br];
  if (r > d) return;
  const float *Wk, *bk; sel(pk, br, Wk, bk);
  const float* G = g_G + br * GSTRIDE;
  float* T = g_T + br * GSTRIDE;
  __shared__ float gsh[192];
  int t = threadIdx.x;               // 192
  gsh[t] = (t <= d) ? G[r * LDD + t] : 0.f;
  __syncthreads();
  if (t < d) {
    float s = gsh[d] * bk[t];
#pragma unroll 4
    for (int ss = 0; ss < d; ss++) s += gsh[ss] * Wk[ss * d + t];
    T[r * LDD + t] = s;
  }
}

// S row p = Wq-hat[:,p]^T @ T, fused softmax, write P transposed
__global__ void k3b_all(P3 pq) {
  const int dTab[3] = {140, 112, 160};
  int br = blockIdx.x / 160;
  int p  = blockIdx.x - br * 160;
  int d = dTab[br];
  if (p >= d) return;
  const float *Wq, *bq; sel(pq, br, Wq, bq);
  const float* T = g_T + br * GSTRIDE;
  float* Pt = g_Pt + br * GSTRIDE;
  __shared__ float wq[192];
  __shared__ float red[256];
  int t = threadIdx.x;               // 256
  int D = d + 1;
  if (t < 192) wq[t] = (t < d) ? Wq[t * d + p] : ((t == d) ? bq[p] : 0.f);
  __syncthreads();
  float s = -3.0e38f;
  if (t < d) {
    s = 0.f;
#pragma unroll 4
    for (int r = 0; r < D; r++) s += wq[r] * T[r * LDD + t];
  }
  red[t] = s; __syncthreads();
  for (int o = 128; o > 0; o >>= 1) { if (t < o) red[t] = fmaxf(red[t], red[t + o]); __syncthreads(); }
  float mx = red[0]; __syncthreads();
  float e = (t < d) ? expf(s - mx) : 0.f;
  red[t] = e; __syncthreads();
  for (int o = 128; o > 0; o >>= 1) { if (t < o) red[t] += red[t + o]; __syncthreads(); }
  float inv = 1.f / red[0];
  if (t < d) Pt[t * LDD + p] = e * inv;
}

// W' row j = Wv-hat[j,:] @ P^T
__global__ void k3d_all(P3 pv) {
  const int dTab[3] = {140, 112, 160};
  int br = blockIdx.x / 161;
  int j  = blockIdx.x - br * 161;
  int d = dTab[br];
  if (j > d) return;
  const float *Wv, *bv; sel(pv, br, Wv, bv);
  const float* Pt = g_Pt + br * GSTRIDE;
  float* Wp = g_Wp + br * GSTRIDE;
  __shared__ float wv[192];
  int t = threadIdx.x;               // 192
  if (t < d) wv[t] = (j < d) ? Wv[j * d + t] : bv[t];
  __syncthreads();
  if (t < d) {
    float s = 0.f;
#pragma unroll 4
    for (int l = 0; l < d; l++) s += wv[l] * Pt[l * LDD + t];
    Wp[j * LDD + t] = s;
  }
}

// ---------------- GEMM2: cross = B-hat @ W', 128x64 tile, 8x8 micro, fused scatter ----------------
template<int BR>
__global__ void __launch_bounds__(128, 4) gemm2_kernel(float* __restrict__ out) {
  constexpr int d  = Tr<BR>::d;
  constexpr int w0 = Tr<BR>::w0, w1 = Tr<BR>::w1, w2 = Tr<BR>::w2;
  constexpr int s0 = Tr<BR>::s0, s1 = Tr<BR>::s1, s2 = Tr<BR>::s2;
  constexpr int pb0 = Tr<BR>::pb0, pb1 = Tr<BR>::pb1, pb2 = Tr<BR>::pb2;
  constexpr int KK = ((d + 1 + 15) / 16) * 16;
  int m0 = blockIdx.x * 128;
  int n0 = blockIdx.y * 64;
  const float* Bg = g_B + (size_t)BR * AB_STRIDE;
  const float* Wp = g_Wp + BR * GSTRIDE;
  __shared__ alignas(16) float Bs[16][128];    // transposed: Bs[k][m]
  __shared__ alignas(16) float Ws[16][64];
  float acc[8][8] = {};
  int t = threadIdx.x;               // 128 threads
  int tx = t & 7, ty = t >> 3;       // tx: n (0..7), ty: m (0..15)
  int lk = t >> 4, lc = (t & 15) * 4;
  float4 pbv[4], pwv[2];
#define G2_LD(K0)                                                          \
  {                                                                        \
    _Pragma("unroll")                                                      \
    for (int jj = 0; jj < 4; jj++)                                         \
      pbv[jj] = *(const float4*)(Bg + (size_t)(m0 + t) * LDD + (K0) + jj * 4); \
    pwv[0] = *(const float4*)(Wp + (size_t)((K0) + lk)     * LDD + n0 + lc);   \
    pwv[1] = *(const float4*)(Wp + (size_t)((K0) + lk + 8) * LDD + n0 + lc);   \
  }
  G2_LD(0);
  for (int k0 = 0; k0 < KK; k0 += 16) {
    __syncthreads();
#pragma unroll
    for (int jj = 0; jj < 4; jj++) {
      Bs[jj * 4 + 0][t] = pbv[jj].x;
      Bs[jj * 4 + 1][t] = pbv[jj].y;
      Bs[jj * 4 + 2][t] = pbv[jj].z;
      Bs[jj * 4 + 3][t] = pbv[jj].w;
    }
    *(float4*)&Ws[lk][lc]     = pwv[0];
    *(float4*)&Ws[lk + 8][lc] = pwv[1];
    __syncthreads();
    if (k0 + 16 < KK) G2_LD(k0 + 16);
#pragma unroll
    for (int k = 0; k < 16; k++) {
      float a[8], b[8];
      *(float4*)&a[0] = *(float4*)&Bs[k][ty * 8];
      *(float4*)&a[4] = *(float4*)&Bs[k][ty * 8 + 4];
      *(float4*)&b[0] = *(float4*)&Ws[k][tx * 8];
      *(float4*)&b[4] = *(float4*)&Ws[k][tx * 8 + 4];
#pragma unroll
      for (int i = 0; i < 8; i++)
#pragma unroll
        for (int j = 0; j < 8; j++)
          acc[i][j] += a[i] * b[j];
    }
  }
#undef G2_LD
  // epilogue: fold + crop + branch transpose, direct to output
  int rc[8], ra[8], rb[8], rcc[8];
#pragma unroll
  for (int i = 0; i < 8; i++) {
    int m = m0 + ty * 8 + i;
    int c = m / 1000;
    int rem = m - c * 1000;
    rc[i]  = c;
    ra[i]  = (rem / 100) * w0 - pb0;
    rb[i]  = ((rem / 10) % 10) * w1 - pb1;
    rcc[i] = (rem % 10) * w2 - pb2;
  }
  int cx[8], cy[8], cz[8]; bool cok[8];
#pragma unroll
  for (int j = 0; j < 8; j++) {
    int col = n0 + tx * 8 + j;
    cok[j] = col < d;
    cx[j] = col / (w1 * w2);
    cy[j] = (col / w2) % w1;
    cz[j] = col % w2;
  }
#pragma unroll
  for (int i = 0; i < 8; i++) {
#pragma unroll
    for (int j = 0; j < 8; j++) {
      if (cok[j]) {
        int u0 = ra[i] + cx[j];
        int u1 = rb[i] + cy[j];
        int u2 = rcc[i] + cz[j];
        if ((unsigned)u0 < (unsigned)s0 && (unsigned)u1 < (unsigned)s1 && (unsigned)u2 < (unsigned)s2) {
          long dst;
          if (BR == 0)      dst = ((long)(rc[i] * 48 + u0) * 66 + u1) * 38 + u2;
          else if (BR == 1) dst = ((long)(rc[i] * 38 + u0) * 66 + u2) * 38 + u1;
          else              dst = ((long)(rc[i] * 48 + u2) * 78 + u1) * 38 + u0;
          out[Tr<BR>::OFF + dst] = acc[i][j];
        }
      }
    }
  }
}

// ---------------- host driver ----------------
extern "C" void kernel_launch(void* const* d_in, const int* in_sizes, int n_in,
                              void* d_out, int out_size) {
  const float* axi   = (const float*)d_in[0];
  const float* cor   = (const float*)d_in[1];
  const float* sag   = (const float*)d_in[2];
  const float* atlas = (const float*)d_in[3];
  float* out = (float*)d_out;

  P3 pq = { (const float*)d_in[4],  (const float*)d_in[5],
            (const float*)d_in[10], (const float*)d_in[11],
            (const float*)d_in[16], (const float*)d_in[17] };
  P3 pk = { (const float*)d_in[6],  (const float*)d_in[7],
            (const float*)d_in[12], (const float*)d_in[13],
            (const float*)d_in[18], (const float*)d_in[19] };
  P3 pv = { (const float*)d_in[8],  (const float*)d_in[9],
            (const float*)d_in[14], (const float*)d_in[15],
            (const float*)d_in[20], (const float*)d_in[21] };

  const int NS = 56;
  const int CHUNK = (M_TOTAL + NS - 1) / NS;

  zero_all<<<(3 * GSTRIDE + 255) / 256, 256>>>();
  packB_all<<<dim3(6400, 3), 256>>>(axi, cor, sag);

  packA_kernel<0><<<6400, 256>>>(atlas);
  gemm1_kernel<0><<<dim3(3, 3, NS), 64>>>(CHUNK);
  packA_kernel<1><<<6400, 256>>>(atlas);
  gemm1_kernel<1><<<dim3(2, 2, NS), 64>>>(CHUNK);
  packA_kernel<2><<<6400, 256>>>(atlas);
  gemm1_kernel<2><<<dim3(3, 3, NS), 64>>>(CHUNK);

  k3a_all<<<3 * 161, 192>>>(pk);
  k3b_all<<<3 * 160, 256>>>(pq);
  k3d_all<<<3 * 161, 192>>>(pv);

  gemm2_kernel<0><<<dim3(500, 3), 128>>>(out);
  gemm2_kernel<1><<<dim3(500, 2), 128>>>(out);
  gemm2_kernel<2><<<dim3(500, 3), 128>>>(out);
}

// round 8
// speedup vs baseline: 1.2150x; 1.0300x over previous
#include <cuda_runtime.h>

#define LDD 192
#define M_TOTAL 64000
#define AB_STRIDE ((size_t)M_TOTAL * LDD)
#define GSTRIDE (LDD * LDD)

// ---------------- scratch (static device globals; keep total well under ~256 MB) ----------------
static __device__ float g_B[3 * AB_STRIDE];   // ~147 MB (branch-batched)
static __device__ float g_A[AB_STRIDE];       // ~49 MB (shared, per-branch reuse)
static __device__ float g_G[3 * GSTRIDE];
static __device__ float g_T[3 * GSTRIDE];
static __device__ float g_Pt[3 * GSTRIDE];
static __device__ float g_Wp[3 * GSTRIDE];

// ---------------- per-branch compile-time traits ----------------
template<int BR> struct Tr;
template<> struct Tr<0> { // axi: s=(48,66,38) w=(5,7,4) d=140 pb=(1,2,1)
  static constexpr int w0=5,w1=7,w2=4,d=140,nt=3;
  static constexpr int s0=48,s1=66,s2=38;
  static constexpr int pb0=1,pb1=2,pb2=1;
  static constexpr long OFF=0;
};
template<> struct Tr<1> { // cor (internal transpose 0,1,2,4,3): s=(38,38,66) w=(4,4,7) d=112 pb=(1,1,2)
  static constexpr int w0=4,w1=4,w2=7,d=112,nt=2;
  static constexpr int s0=38,s1=38,s2=66;
  static constexpr int pb0=1,pb1=1,pb2=2;
  static constexpr long OFF=7704576;
};
template<> struct Tr<2> { // sag (internal transpose 0,1,4,3,2): s=(38,78,48) w=(4,8,5) d=160 pb=(1,1,1)
  static constexpr int w0=4,w1=8,w2=5,d=160,nt=3;
  static constexpr int s0=38,s1=78,s2=48;
  static constexpr int pb0=1,pb1=1,pb2=1;
  static constexpr long OFF=13804032;
};

template<int BR>
__device__ __forceinline__ void amap(int x, int y, int z, int& xb, int& yb, int& zb) {
  if (BR == 0) {
    xb = x; yb = (y * 6) / 7; zb = z;
  } else if (BR == 1) {
    int x2 = (x * 5) / 4, y2 = (y * 7) / 4, z2 = (z * 4) / 7;
    xb = x2; yb = (y2 * 6) / 7; zb = z2;
  } else {
    int y3 = y / 2, z3 = (z * 7) / 5;
    int x2 = (x * 5) / 4, y2 = (y3 * 7) / 4, z2 = (z3 * 4) / 7;
    xb = x2; yb = (y2 * 6) / 7; zb = z2;
  }
}

// ---------------- packB: gather B-hat for all branches in one launch ----------------
template<int BR>
__device__ void packB_body(const float* __restrict__ feat) {
  constexpr int w0=Tr<BR>::w0, w1=Tr<BR>::w1, w2=Tr<BR>::w2, d=Tr<BR>::d;
  constexpr int s0=Tr<BR>::s0, s1=Tr<BR>::s1, s2=Tr<BR>::s2;
  constexpr int pb0=Tr<BR>::pb0, pb1=Tr<BR>::pb1, pb2=Tr<BR>::pb2;
  float* Bdst = g_B + (size_t)BR * AB_STRIDE;
  int blk = blockIdx.x;
  int c = blk / 100;
  int a = (blk / 10) % 10;
  int b = blk % 10;
  for (int t = threadIdx.x; t < 10 * LDD; t += blockDim.x) {
    int cc = t / LDD;
    int j  = t - cc * LDD;
    int row = blk * 10 + cc;
    float vB;
    if (j < d) {
      int x = j / (w1 * w2);
      int y = (j / w2) % w1;
      int z = j % w2;
      int i0 = a * w0 + x - pb0;
      int i1 = b * w1 + y - pb1;
      int i2 = cc * w2 + z - pb2;
      vB = 0.f;
      if ((unsigned)i0 < (unsigned)s0 && (unsigned)i1 < (unsigned)s1 && (unsigned)i2 < (unsigned)s2) {
        int src;
        if (BR == 0)      src = ((c * 48 + i0) * 66 + i1) * 38 + i2;
        else if (BR == 1) src = ((c * 38 + i0) * 66 + i2) * 38 + i1;
        else              src = ((c * 48 + i2) * 78 + i1) * 38 + i0;
        vB = feat[src];
      }
    } else {
      vB = (j == d) ? 1.f : 0.f;
    }
    Bdst[(size_t)row * LDD + j] = vB;
  }
}

__global__ void packB_all(const float* __restrict__ axi, const float* __restrict__ cor,
                          const float* __restrict__ sag) {
  if (blockIdx.y == 0)      packB_body<0>(axi);
  else if (blockIdx.y == 1) packB_body<1>(cor);
  else                      packB_body<2>(sag);
}

// ---------------- packA: gather A-hat for one branch into shared buffer ----------------
template<int BR>
__global__ void packA_kernel(const float* __restrict__ atlas) {
  constexpr int w1=Tr<BR>::w1, w2=Tr<BR>::w2, d=Tr<BR>::d;
  int blk = blockIdx.x;
  int a = (blk / 10) % 10;
  int b = blk % 10;
  int c = blk / 100;
  for (int t = threadIdx.x; t < 10 * LDD; t += blockDim.x) {
    int cc = t / LDD;
    int j  = t - cc * LDD;
    int row = blk * 10 + cc;
    float vA;
    if (j < d) {
      int x = j / (w1 * w2);
      int y = (j / w2) % w1;
      int z = j % w2;
      int xb, yb, zb;
      amap<BR>(x, y, z, xb, yb, zb);
      int j0 = a * 5 + xb - 2;   // atlas aw=(5,6,4), pb=(2,2,1)
      int j1 = b * 6 + yb - 2;
      int j2 = cc * 4 + zb - 1;
      vA = 0.f;
      if ((unsigned)j0 < 46u && (unsigned)j1 < 56u && (unsigned)j2 < 38u)
        vA = atlas[((c * 46 + j0) * 56 + j1) * 38 + j2];
    } else {
      vA = (j == d) ? 1.f : 0.f;
    }
    g_A[(size_t)row * LDD + j] = vA;
  }
}

__global__ void zero_all() {
  int i = blockIdx.x * blockDim.x + threadIdx.x;
  if (i < 3 * GSTRIDE) { g_G[i] = 0.f; g_Wp[i] = 0.f; }
}

// ---------------- GEMM1: G = A-hat^T * B-hat, one branch, split-M, 8x8 micro ----------------
template<int BR>
__global__ void __launch_bounds__(64, 8) gemm1_kernel(int mChunk) {
  int p0 = blockIdx.x * 64;
  int q0 = blockIdx.y * 64;
  int m0 = blockIdx.z * mChunk;
  int mHi = min(m0 + mChunk, M_TOTAL);
  if (m0 >= mHi) return;
  const float* A  = g_A;
  const float* Bp = g_B + (size_t)BR * AB_STRIDE;
  float* G = g_G + BR * GSTRIDE;
  __shared__ alignas(16) float As[16][64];
  __shared__ alignas(16) float Bs[16][64];
  float acc[8][8] = {};
  int t = threadIdx.x;               // 64 threads
  int tx = t & 7, ty = t >> 3;
  int lr = t >> 4, lc = (t & 15) * 4;
  float4 pa[4], pb[4];
#define G1_LD(MB)                                                        \
  {                                                                      \
    _Pragma("unroll")                                                    \
    for (int i = 0; i < 4; i++) {                                        \
      int row = (MB) + lr + i * 4;                                       \
      if (row < mHi) {                                                   \
        pa[i] = *(const float4*)(A  + (size_t)row * LDD + p0 + lc);      \
        pb[i] = *(const float4*)(Bp + (size_t)row * LDD + q0 + lc);      \
      } else { pa[i] = make_float4(0.f,0.f,0.f,0.f); pb[i] = pa[i]; }    \
    }                                                                    \
  }
  G1_LD(m0);
  for (int mb = m0; mb < mHi; mb += 16) {
    __syncthreads();
#pragma unroll
    for (int i = 0; i < 4; i++) {
      *(float4*)&As[lr + i * 4][lc] = pa[i];
      *(float4*)&Bs[lr + i * 4][lc] = pb[i];
    }
    __syncthreads();
    if (mb + 16 < mHi) G1_LD(mb + 16);
#pragma unroll
    for (int k = 0; k < 16; k++) {
      float a[8], b[8];
      *(float4*)&a[0] = *(float4*)&As[k][ty * 8];
      *(float4*)&a[4] = *(float4*)&As[k][ty * 8 + 4];
      *(float4*)&b[0] = *(float4*)&Bs[k][tx * 8];
      *(float4*)&b[4] = *(float4*)&Bs[k][tx * 8 + 4];
#pragma unroll
      for (int i = 0; i < 8; i++)
#pragma unroll
        for (int j = 0; j < 8; j++)
          acc[i][j] += a[i] * b[j];
    }
  }
#pragma unroll
  for (int i = 0; i < 8; i++)
#pragma unroll
    for (int j = 0; j < 8; j++)
      atomicAdd(&G[(p0 + ty * 8 + i) * LDD + q0 + tx * 8 + j], acc[i][j]);
#undef G1_LD
}

// ---------------- small chain (batched across branches) ----------------
struct P3 { const float* W0; const float* b0; const float* W1; const float* b1;
            const float* W2; const float* b2; };

__device__ __forceinline__ void sel(const P3& p, int br, const float*& W, const float*& b) {
  if (br == 0)      { W = p.W0; b = p.b0; }
  else if (br == 1) { W = p.W1; b = p.b1; }
  else              { W = p.W2; b = p.b2; }
}

// T = G-hat @ Wk-hat
__global__ void k3a_all(P3 pk) {
  const int dTab[3] = {140, 112, 160};
  int br = blockIdx.x / 161;
  int r  = blockIdx.x - br * 161;
  int d = dTab[br];
  if (r > d) return;
  const float *Wk, *bk; sel(pk, br, Wk, bk);
  const float* G = g_G + br * GSTRIDE;
  float* T = g_T + br * GSTRIDE;
  __shared__ float gsh[192];
  int t = threadIdx.x;               // 192
  gsh[t] = (t <= d) ? G[r * LDD + t] : 0.f;
  __syncthreads();
  if (t < d) {
    float s = gsh[d] * bk[t];
#pragma unroll 4
    for (int ss = 0; ss < d; ss++) s += gsh[ss] * Wk[ss * d + t];
    T[r * LDD + t] = s;
  }
}

// S row p = Wq-hat[:,p]^T @ T, fused softmax, write P transposed
__global__ void k3b_all(P3 pq) {
  const int dTab[3] = {140, 112, 160};
  int br = blockIdx.x / 160;
  int p  = blockIdx.x - br * 160;
  int d = dTab[br];
  if (p >= d) return;
  const float *Wq, *bq; sel(pq, br, Wq, bq);
  const float* T = g_T + br * GSTRIDE;
  float* Pt = g_Pt + br * GSTRIDE;
  __shared__ float wq[192];
  __shared__ float red[256];
  int t = threadIdx.x;               // 256
  int D = d + 1;
  if (t < 192) wq[t] = (t < d) ? Wq[t * d + p] : ((t == d) ? bq[p] : 0.f);
  __syncthreads();
  float s = -3.0e38f;
  if (t < d) {
    s = 0.f;
#pragma unroll 4
    for (int r = 0; r < D; r++) s += wq[r] * T[r * LDD + t];
  }
  red[t] = s; __syncthreads();
  for (int o = 128; o > 0; o >>= 1) { if (t < o) red[t] = fmaxf(red[t], red[t + o]); __syncthreads(); }
  float mx = red[0]; __syncthreads();
  float e = (t < d) ? expf(s - mx) : 0.f;
  red[t] = e; __syncthreads();
  for (int o = 128; o > 0; o >>= 1) { if (t < o) red[t] += red[t + o]; __syncthreads(); }
  float inv = 1.f / red[0];
  if (t < d) Pt[t * LDD + p] = e * inv;
}

// W' row j = Wv-hat[j,:] @ P^T
__global__ void k3d_all(P3 pv) {
  const int dTab[3] = {140, 112, 160};
  int br = blockIdx.x / 161;
  int j  = blockIdx.x - br * 161;
  int d = dTab[br];
  if (j > d) return;
  const float *Wv, *bv; sel(pv, br, Wv, bv);
  const float* Pt = g_Pt + br * GSTRIDE;
  float* Wp = g_Wp + br * GSTRIDE;
  __shared__ float wv[192];
  int t = threadIdx.x;               // 192
  if (t < d) wv[t] = (j < d) ? Wv[j * d + t] : bv[t];
  __syncthreads();
  if (t < d) {
    float s = 0.f;
#pragma unroll 4
    for (int l = 0; l < d; l++) s += wv[l] * Pt[l * LDD + t];
    Wp[j * LDD + t] = s;
  }
}

// ---------------- GEMM2: cross = B-hat @ W', 128x64 tile, 8x8 micro, fused scatter ----------------
template<int BR>
__global__ void __launch_bounds__(128, 4) gemm2_kernel(float* __restrict__ out) {
  constexpr int d  = Tr<BR>::d;
  constexpr int w0 = Tr<BR>::w0, w1 = Tr<BR>::w1, w2 = Tr<BR>::w2;
  constexpr int s0 = Tr<BR>::s0, s1 = Tr<BR>::s1, s2 = Tr<BR>::s2;
  constexpr int pb0 = Tr<BR>::pb0, pb1 = Tr<BR>::pb1, pb2 = Tr<BR>::pb2;
  constexpr int KK = ((d + 1 + 15) / 16) * 16;
  int m0 = blockIdx.x * 128;
  int n0 = blockIdx.y * 64;
  const float* Bg = g_B + (size_t)BR * AB_STRIDE;
  const float* Wp = g_Wp + BR * GSTRIDE;
  __shared__ alignas(16) float Bs[16][128];    // transposed: Bs[k][m]
  __shared__ alignas(16) float Ws[16][64];
  float acc[8][8] = {};
  int t = threadIdx.x;               // 128 threads
  int tx = t & 7, ty = t >> 3;       // tx: n (0..7), ty: m (0..15)
  int lk = t >> 4, lc = (t & 15) * 4;
  float4 pbv[4], pwv[2];
#define G2_LD(K0)                                                          \
  {                                                                        \
    _Pragma("unroll")                                                      \
    for (int jj = 0; jj < 4; jj++)                                         \
      pbv[jj] = *(const float4*)(Bg + (size_t)(m0 + t) * LDD + (K0) + jj * 4); \
    pwv[0] = *(const float4*)(Wp + (size_t)((K0) + lk)     * LDD + n0 + lc);   \
    pwv[1] = *(const float4*)(Wp + (size_t)((K0) + lk + 8) * LDD + n0 + lc);   \
  }
  G2_LD(0);
  for (int k0 = 0; k0 < KK; k0 += 16) {
    __syncthreads();
#pragma unroll
    for (int jj = 0; jj < 4; jj++) {
      Bs[jj * 4 + 0][t] = pbv[jj].x;
      Bs[jj * 4 + 1][t] = pbv[jj].y;
      Bs[jj * 4 + 2][t] = pbv[jj].z;
      Bs[jj * 4 + 3][t] = pbv[jj].w;
    }
    *(float4*)&Ws[lk][lc]     = pwv[0];
    *(float4*)&Ws[lk + 8][lc] = pwv[1];
    __syncthreads();
    if (k0 + 16 < KK) G2_LD(k0 + 16);
#pragma unroll
    for (int k = 0; k < 16; k++) {
      float a[8], b[8];
      *(float4*)&a[0] = *(float4*)&Bs[k][ty * 8];
      *(float4*)&a[4] = *(float4*)&Bs[k][ty * 8 + 4];
      *(float4*)&b[0] = *(float4*)&Ws[k][tx * 8];
      *(float4*)&b[4] = *(float4*)&Ws[k][tx * 8 + 4];
#pragma unroll
      for (int i = 0; i < 8; i++)
#pragma unroll
        for (int j = 0; j < 8; j++)
          acc[i][j] += a[i] * b[j];
    }
  }
#undef G2_LD
  // epilogue: fold + crop + branch transpose, direct to output
  int rc[8], ra[8], rb[8], rcc[8];
#pragma unroll
  for (int i = 0; i < 8; i++) {
    int m = m0 + ty * 8 + i;
    int c = m / 1000;
    int rem = m - c * 1000;
    rc[i]  = c;
    ra[i]  = (rem / 100) * w0 - pb0;
    rb[i]  = ((rem / 10) % 10) * w1 - pb1;
    rcc[i] = (rem % 10) * w2 - pb2;
  }
  int cx[8], cy[8], cz[8]; bool cok[8];
#pragma unroll
  for (int j = 0; j < 8; j++) {
    int col = n0 + tx * 8 + j;
    cok[j] = col < d;
    cx[j] = col / (w1 * w2);
    cy[j] = (col / w2) % w1;
    cz[j] = col % w2;
  }
#pragma unroll
  for (int i = 0; i < 8; i++) {
#pragma unroll
    for (int j = 0; j < 8; j++) {
      if (cok[j]) {
        int u0 = ra[i] + cx[j];
        int u1 = rb[i] + cy[j];
        int u2 = rcc[i] + cz[j];
        if ((unsigned)u0 < (unsigned)s0 && (unsigned)u1 < (unsigned)s1 && (unsigned)u2 < (unsigned)s2) {
          long dst;
          if (BR == 0)      dst = ((long)(rc[i] * 48 + u0) * 66 + u1) * 38 + u2;
          else if (BR == 1) dst = ((long)(rc[i] * 38 + u0) * 66 + u2) * 38 + u1;
          else              dst = ((long)(rc[i] * 48 + u2) * 78 + u1) * 38 + u0;
          out[Tr<BR>::OFF + dst] = acc[i][j];
        }
      }
    }
  }
}

// ---------------- host driver ----------------
extern "C" void kernel_launch(void* const* d_in, const int* in_sizes, int n_in,
                              void* d_out, int out_size) {
  const float* axi   = (const float*)d_in[0];
  const float* cor   = (const float*)d_in[1];
  const float* sag   = (const float*)d_in[2];
  const float* atlas = (const float*)d_in[3];
  float* out = (float*)d_out;

  P3 pq = { (const float*)d_in[4],  (const float*)d_in[5],
            (const float*)d_in[10], (const float*)d_in[11],
            (const float*)d_in[16], (const float*)d_in[17] };
  P3 pk = { (const float*)d_in[6],  (const float*)d_in[7],
            (const float*)d_in[12], (const float*)d_in[13],
            (const float*)d_in[18], (const float*)d_in[19] };
  P3 pv = { (const float*)d_in[8],  (const float*)d_in[9],
            (const float*)d_in[14], (const float*)d_in[15],
            (const float*)d_in[20], (const float*)d_in[21] };

  // split-M factors tuned for ~8 blocks/SM (148 SMs, 64-thread blocks)
  const int NS0 = 128, CH0 = (M_TOTAL + NS0 - 1) / NS0;   // 9 tiles * 128 = 1152 blocks
  const int NS1 = 288, CH1 = (M_TOTAL + NS1 - 1) / NS1;   // 4 tiles * 288 = 1152 blocks
  const int NS2 = 128, CH2 = (M_TOTAL + NS2 - 1) / NS2;

  zero_all<<<(3 * GSTRIDE + 255) / 256, 256>>>();
  packB_all<<<dim3(6400, 3), 256>>>(axi, cor, sag);

  packA_kernel<0><<<6400, 256>>>(atlas);
  gemm1_kernel<0><<<dim3(3, 3, NS0), 64>>>(CH0);
  packA_kernel<1><<<6400, 256>>>(atlas);
  gemm1_kernel<1><<<dim3(2, 2, NS1), 64>>>(CH1);
  packA_kernel<2><<<6400, 256>>>(atlas);
  gemm1_kernel<2><<<dim3(3, 3, NS2), 64>>>(CH2);

  k3a_all<<<3 * 161, 192>>>(pk);
  k3b_all<<<3 * 160, 256>>>(pq);
  k3d_all<<<3 * 161, 192>>>(pv);

  gemm2_kernel<0><<<dim3(500, 3), 128>>>(out);
  gemm2_kernel<1><<<dim3(500, 2), 128>>>(out);
  gemm2_kernel<2><<<dim3(500, 3), 128>>>(out);
}